// round 16
// baseline (speedup 1.0000x reference)
#include <cuda_runtime.h>
#include <cuda_fp16.h>
#include <cstdint>

// x:      [4, 512, 64, 64]  fp32
// w_qkv:  [1536, 512], b_qkv: [1536]
// w_proj: [512, 512],  b_proj: [512]
// out:    [4, 512, 64, 64]  fp32
//
// g_q16/g_k16b: [b,h,tok(4096)][d2(32)] half2 (d even, d odd)
// g_vt:         [b,h,d(64)][tok(4096)]  half (transposed V)
// blobs:        [tile128][kchunk32][k2(16)][row(128)] half2

__device__ uint32_t g_q16[4 * 8 * 4096 * 32];
__device__ __align__(16) uint32_t g_k16b[4 * 8 * 4096 * 32];
__device__ __align__(16) __half g_vt[4 * 8 * 64 * 4096];
__device__ __align__(16) __half2 g_wqb[ 12 * 16 * 16 * 128];
__device__ __align__(16) __half2 g_wpb[  4 * 16 * 16 * 128];
__device__ __align__(16) __half2 g_ob [128 * 16 * 16 * 128];

__device__ __forceinline__ uint32_t pack2(float x, float y) {
    __half2 h = __floats2half2_rn(x, y);
    return *(uint32_t*)&h;
}

// scale = 0.125 * log2(e): softmax computed in base-2 domain
__device__ __forceinline__ uint32_t h2scaleq(uint32_t v) {
    __half2 h = *(__half2*)&v;
    h = __hmul2(h, __float2half2_rn(0.18033688f));
    return *(uint32_t*)&h;
}

__device__ __forceinline__ float ex2(float x) {
    float y;
    asm("ex2.approx.f32 %0, %1;" : "=f"(y) : "f"(x));
    return y;
}

__device__ __forceinline__ void mma_f16(float c[4], const uint32_t a[4],
                                        uint32_t b0, uint32_t b1) {
    asm volatile(
        "mma.sync.aligned.m16n8k16.row.col.f32.f16.f16.f32 "
        "{%0,%1,%2,%3}, {%4,%5,%6,%7}, {%8,%9}, {%0,%1,%2,%3};"
        : "+f"(c[0]), "+f"(c[1]), "+f"(c[2]), "+f"(c[3])
        : "r"(a[0]), "r"(a[1]), "r"(a[2]), "r"(a[3]), "r"(b0), "r"(b1));
}

__device__ __forceinline__ void ldm4(uint32_t& f0, uint32_t& f1,
                                     uint32_t& f2, uint32_t& f3, uint32_t addr) {
    asm volatile("ldmatrix.sync.aligned.m8n8.x4.shared.b16 {%0,%1,%2,%3}, [%4];"
                 : "=r"(f0), "=r"(f1), "=r"(f2), "=r"(f3) : "r"(addr));
}

__device__ __forceinline__ void cpa16(uint32_t dst_s, const void* src) {
    asm volatile("cp.async.ca.shared.global [%0], [%1], 16;"
                 :: "r"(dst_s), "l"(src) : "memory");
}

// ---------------------------------------------------------------------------
// prep: weight blobs
// ---------------------------------------------------------------------------
__global__ __launch_bounds__(256) void prep_wq(const float* __restrict__ w) {
    __shared__ float tile[32][33];
    const int n0 = blockIdx.x * 32, k0 = blockIdx.y * 32;
    const int tx = threadIdx.x & 31, ty = threadIdx.x >> 5;
    #pragma unroll
    for (int j = 0; j < 32; j += 8)
        tile[ty + j][tx] = w[(n0 + ty + j) * 512 + k0 + tx];
    __syncthreads();
    const int n  = n0 + tx;
    const int nt = n >> 7, nl = n & 127, kc = k0 >> 5;
    #pragma unroll
    for (int pp = 0; pp < 2; pp++) {
        int p = ty + pp * 8;
        g_wqb[((nt * 16 + kc) * 16 + p) * 128 + nl] =
            __floats2half2_rn(tile[tx][2 * p], tile[tx][2 * p + 1]);
    }
}

__global__ __launch_bounds__(256) void prep_wp(const float* __restrict__ w) {
    __shared__ float tile[32][33];
    const int n0 = blockIdx.x * 32, k0 = blockIdx.y * 32;
    const int tx = threadIdx.x & 31, ty = threadIdx.x >> 5;
    #pragma unroll
    for (int j = 0; j < 32; j += 8)
        tile[ty + j][tx] = w[(n0 + ty + j) * 512 + k0 + tx];
    __syncthreads();
    const int n  = n0 + tx;
    const int nt = n >> 7, nl = n & 127, kc = k0 >> 5;
    #pragma unroll
    for (int pp = 0; pp < 2; pp++) {
        int p = ty + pp * 8;
        g_wpb[((nt * 16 + kc) * 16 + p) * 128 + nl] =
            __floats2half2_rn(tile[tx][2 * p], tile[tx][2 * p + 1]);
    }
}

// ---------------------------------------------------------------------------
// Kernel 1: QKV GEMM, fused x transpose+convert (unchanged from R15).
// ---------------------------------------------------------------------------
__global__ __launch_bounds__(128) void qkv_f16(const float* __restrict__ x,
                                               const float* __restrict__ bias)
{
    __shared__ __align__(16) uint32_t As[2][16][136];
    __shared__ __align__(16) uint32_t Bs[2][16][136];

    const int t    = threadIdx.x;
    const int lane = t & 31, warp = t >> 5;
    const int g    = lane >> 2, tig = lane & 3;
    const int wm   = warp >> 1, wn = warp & 1;

    const int m0 = blockIdx.y * 128, n0 = blockIdx.x * 128;
    const int b  = m0 >> 12, sp0 = m0 & 4095;

    const float* xb = x + (((size_t)b * 512) << 12) + sp0;
    const uint4* Bb = (const uint4*)(g_wqb + (size_t)blockIdx.x * 32768);
    const uint32_t bs_s = (uint32_t)__cvta_generic_to_shared(&Bs[0][0][0]);

    float acc[4][8][4] = {};
    float4 fa[8];

    #pragma unroll
    for (int r = 0; r < 4; r++) {
        int e = r * 128 + t;
        int k2 = e >> 5, m4 = (e & 31) << 2;
        fa[2 * r]     = *(const float4*)&xb[((size_t)(2 * k2)     << 12) + m4];
        fa[2 * r + 1] = *(const float4*)&xb[((size_t)(2 * k2 + 1) << 12) + m4];
    }
    #pragma unroll
    for (int r = 0; r < 4; r++) {
        int e = r * 128 + t;
        int row = e >> 5, col4 = (e & 31) << 2;
        cpa16(bs_s + (row * 136 + col4) * 4, Bb + e);
    }
    asm volatile("cp.async.commit_group;");

    #pragma unroll 1
    for (int c = 0; c < 16; c++) {
        int buf = c & 1;
        asm volatile("cp.async.wait_group 0;" ::: "memory");
        #pragma unroll
        for (int r = 0; r < 4; r++) {
            int e = r * 128 + t;
            int k2 = e >> 5, m4 = (e & 31) << 2;
            uint4 u;
            u.x = pack2(fa[2*r].x, fa[2*r+1].x);
            u.y = pack2(fa[2*r].y, fa[2*r+1].y);
            u.z = pack2(fa[2*r].z, fa[2*r+1].z);
            u.w = pack2(fa[2*r].w, fa[2*r+1].w);
            *(uint4*)&As[buf][k2][m4] = u;
        }
        __syncthreads();
        if (c + 1 < 16) {
            int k0 = (c + 1) * 32;
            #pragma unroll
            for (int r = 0; r < 4; r++) {
                int e = r * 128 + t;
                int k2 = e >> 5, m4 = (e & 31) << 2;
                fa[2 * r]     = *(const float4*)&xb[((size_t)(k0 + 2 * k2)     << 12) + m4];
                fa[2 * r + 1] = *(const float4*)&xb[((size_t)(k0 + 2 * k2 + 1) << 12) + m4];
            }
            #pragma unroll
            for (int r = 0; r < 4; r++) {
                int e = r * 128 + t;
                int row = e >> 5, col4 = (e & 31) << 2;
                cpa16(bs_s + (((buf ^ 1) * 16 * 136) + row * 136 + col4) * 4,
                      Bb + (c + 1) * 512 + e);
            }
            asm volatile("cp.async.commit_group;");
        }
        #pragma unroll
        for (int ks = 0; ks < 2; ks++) {
            uint32_t af[4][4];
            #pragma unroll
            for (int mt = 0; mt < 4; mt++) {
                int m = wm * 64 + mt * 16 + g;
                af[mt][0] = As[buf][ks * 8 + tig    ][m];
                af[mt][1] = As[buf][ks * 8 + tig    ][m + 8];
                af[mt][2] = As[buf][ks * 8 + tig + 4][m];
                af[mt][3] = As[buf][ks * 8 + tig + 4][m + 8];
            }
            #pragma unroll
            for (int nt = 0; nt < 8; nt++) {
                int n = wn * 64 + nt * 8 + g;
                uint32_t b0 = Bs[buf][ks * 8 + tig    ][n];
                uint32_t b1 = Bs[buf][ks * 8 + tig + 4][n];
                #pragma unroll
                for (int mt = 0; mt < 4; mt++)
                    mma_f16(acc[mt][nt], af[mt], b0, b1);
            }
        }
        __syncthreads();
    }

    const int which = n0 >> 9, h0 = (n0 >> 6) & 7;
    #pragma unroll
    for (int mt = 0; mt < 4; mt++) {
        #pragma unroll
        for (int nt = 0; nt < 8; nt++) {
            int m    = m0 + wm * 64 + mt * 16 + g;
            int bb   = m >> 12, sp = m & 4095;
            int ncol = wn * 64 + nt * 8 + 2 * tig;
            int h    = h0 + (ncol >> 6);
            int dd   = ncol & 63;
            float bv0 = bias[n0 + ncol], bv1 = bias[n0 + ncol + 1];
            float v00 = acc[mt][nt][0] + bv0, v01 = acc[mt][nt][1] + bv1;
            float v10 = acc[mt][nt][2] + bv0, v11 = acc[mt][nt][3] + bv1;
            if (which < 2) {
                uint32_t* dst16 = (which == 0) ? g_q16 : g_k16b;
                size_t idx = (size_t)(((bb * 8 + h) << 12) + sp) * 32 + (dd >> 1);
                dst16[idx]          = pack2(v00, v01);
                dst16[idx + 8 * 32] = pack2(v10, v11);
            } else {
                size_t idx = ((size_t)((bb * 8 + h) * 64 + dd) << 12) + sp;
                g_vt[idx]            = __float2half_rn(v00);
                g_vt[idx + 4096]     = __float2half_rn(v01);
                g_vt[idx + 8]        = __float2half_rn(v10);
                g_vt[idx + 4096 + 8] = __float2half_rn(v11);
            }
        }
    }
}

// ---------------------------------------------------------------------------
// GEMM core for proj (unchanged)
// ---------------------------------------------------------------------------
__device__ __forceinline__ void gemm_core(const uint4* __restrict__ Ab,
                                          const uint4* __restrict__ Bb,
                                          float acc[4][8][4])
{
    __shared__ __align__(16) uint32_t As[2][16][136];
    __shared__ __align__(16) uint32_t Bs[2][16][136];

    const int t    = threadIdx.x;
    const int lane = t & 31, warp = t >> 5;
    const int g    = lane >> 2, tig = lane & 3;
    const int wm   = warp >> 1, wn = warp & 1;

    uint4 ra[4], rb[4];
    #pragma unroll
    for (int r = 0; r < 4; r++) { ra[r] = Ab[r * 128 + t]; rb[r] = Bb[r * 128 + t]; }

    #pragma unroll 1
    for (int c = 0; c < 16; c++) {
        int buf = c & 1;
        #pragma unroll
        for (int r = 0; r < 4; r++) {
            int e = r * 128 + t;
            *(uint4*)&As[buf][e >> 5][(e & 31) << 2] = ra[r];
            *(uint4*)&Bs[buf][e >> 5][(e & 31) << 2] = rb[r];
        }
        __syncthreads();
        if (c + 1 < 16) {
            #pragma unroll
            for (int r = 0; r < 4; r++) {
                ra[r] = Ab[(c + 1) * 512 + r * 128 + t];
                rb[r] = Bb[(c + 1) * 512 + r * 128 + t];
            }
        }
        #pragma unroll
        for (int ks = 0; ks < 2; ks++) {
            uint32_t af[4][4];
            #pragma unroll
            for (int mt = 0; mt < 4; mt++) {
                int m = wm * 64 + mt * 16 + g;
                af[mt][0] = As[buf][ks * 8 + tig    ][m];
                af[mt][1] = As[buf][ks * 8 + tig    ][m + 8];
                af[mt][2] = As[buf][ks * 8 + tig + 4][m];
                af[mt][3] = As[buf][ks * 8 + tig + 4][m + 8];
            }
            #pragma unroll
            for (int nt = 0; nt < 8; nt++) {
                int n = wn * 64 + nt * 8 + g;
                uint32_t b0 = Bs[buf][ks * 8 + tig    ][n];
                uint32_t b1 = Bs[buf][ks * 8 + tig + 4][n];
                #pragma unroll
                for (int mt = 0; mt < 4; mt++)
                    mma_f16(acc[mt][nt], af[mt], b0, b1);
            }
        }
        __syncthreads();
    }
}

__global__ __launch_bounds__(128) void proj_f16(const float* __restrict__ bias,
                                                float* __restrict__ out)
{
    float acc[4][8][4] = {};
    gemm_core((const uint4*)(g_ob  + (size_t)blockIdx.y * 32768),
              (const uint4*)(g_wpb + (size_t)blockIdx.x * 32768), acc);

    const int t    = threadIdx.x;
    const int lane = t & 31, warp = t >> 5;
    const int g    = lane >> 2, tig = lane & 3;
    const int wm   = warp >> 1, wn = warp & 1;

    const int m0 = blockIdx.y * 128, n0 = blockIdx.x * 128;
    #pragma unroll
    for (int mt = 0; mt < 4; mt++) {
        #pragma unroll
        for (int nt = 0; nt < 8; nt++) {
            int m    = m0 + wm * 64 + mt * 16 + g;
            int bb   = m >> 12, sp = m & 4095;
            int n    = n0 + wn * 64 + nt * 8 + 2 * tig;
            float bv0 = bias[n], bv1 = bias[n + 1];
            float* p0 = &out[((bb * 512 + n) << 12) + sp];
            float* p1 = &out[((bb * 512 + n + 1) << 12) + sp];
            p0[0] = acc[mt][nt][0] + bv0;
            p1[0] = acc[mt][nt][1] + bv1;
            p0[8] = acc[mt][nt][2] + bv0;
            p1[8] = acc[mt][nt][3] + bv1;
        }
    }
}

// ---------------------------------------------------------------------------
// Kernel 2: sliding-chunk attention, fp16 mma + ldmatrix, P in registers,
// K AND V via cp.async into DOUBLE-BUFFERED smem, 1-deep pipeline,
// ONE __syncthreads per pair. 3 CTAs/SM.
// Per buffer: Ks [128 tok][72] half (18432 B), Vt [64 d][136] half (17408 B)
// Buffer stride 35840 B; dynamic smem = 71680 B.
// ---------------------------------------------------------------------------
extern __shared__ __align__(16) __half s_attn_h[];

// issue cp.async for one neighbor pair into the buffer at byte base `base_s`
__device__ __forceinline__ void issue_pair(uint32_t base_s, int nb0, int nb1,
                                           int cy, int cx, int bh, int vb, int t)
{
    #pragma unroll
    for (int hf = 0; hf < 2; hf++) {
        int nn = hf ? nb1 : nb0;
        if (nn < 0) break;
        int ny = cy + nn / 3 - 1, nx = cx + nn % 3 - 1;
        #pragma unroll
        for (int r = 0; r < 4; r++) {
            int e = r * 128 + t;
            int tok = e >> 3, oct = e & 7;
            int y = ny * 8 + (tok >> 3), xx = nx * 8 + (tok & 7);
            // K tile: Ks[hf*64+tok][oct*8 .. +8)
            cpa16(base_s + ((hf * 64 + tok) * 72 + oct * 8) * 2,
                  &g_k16b[(size_t)(bh + y * 64 + xx) * 32 + oct * 4]);
            // V tile: Vt[d=tok][hf*64 + oct*8 .. +8)
            cpa16(base_s + 18432 + (tok * 136 + hf * 64 + oct * 8) * 2,
                  &g_vt[((size_t)(vb + tok) << 12) + (ny * 8 + oct) * 64 + nx * 8]);
        }
    }
    asm volatile("cp.async.commit_group;");
}

__global__ __launch_bounds__(128, 3) void attn_f16(void)
{
    const uint32_t smem_s = (uint32_t)__cvta_generic_to_shared(s_attn_h);

    const int t    = threadIdx.x;
    const int lane = t & 31, warp = t >> 5;
    const int g    = lane >> 2, tig = lane & 3;
    const int mi   = lane >> 3, ri = lane & 7;

    // heavy-first chunk decode
    const int r_cls = blockIdx.x >> 5;
    const int bh_i  = blockIdx.x & 31;
    int cy, cx;
    if (r_cls < 36)      { cy = 1 + r_cls / 6; cx = 1 + r_cls % 6; }
    else if (r_cls < 60) {
        int e = r_cls - 36;
        if (e < 6)       { cy = 0;      cx = 1 + e; }
        else if (e < 12) { cy = 7;      cx = e - 5; }
        else if (e < 18) { cy = e - 11; cx = 0;     }
        else             { cy = e - 17; cx = 7;     }
    } else {
        int c = r_cls - 60;
        cy = (c >> 1) * 7; cx = (c & 1) * 7;
    }
    const int b = bh_i >> 3, h = bh_i & 7;
    const int bh = (b * 8 + h) << 12;
    const int vb = (b * 8 + h) * 64;

    const int row0 = warp * 16 + g;
    const int row1 = row0 + 8;

    // ldmatrix lane-base offsets (bytes, relative to buffer base)
    const uint32_t kaddr_l = ri * 144 + (mi >> 1) * 1152 + (mi & 1) * 16;
    const uint32_t vaddr_l = 18432 + ri * 272 + (mi >> 1) * 2176 + (mi & 1) * 16;

    // Q fragments scaled by 0.125*log2(e)
    uint32_t qf[4][4];
    {
        int y0 = cy * 8 + (row0 >> 3), x0 = cx * 8 + (row0 & 7);
        int y1 = cy * 8 + (row1 >> 3), x1 = cx * 8 + (row1 & 7);
        const uint32_t* q0 = &g_q16[(size_t)(bh + y0 * 64 + x0) * 32];
        const uint32_t* q1 = &g_q16[(size_t)(bh + y1 * 64 + x1) * 32];
        #pragma unroll
        for (int ks = 0; ks < 4; ks++) {
            qf[ks][0] = h2scaleq(q0[ks * 8 + tig]);
            qf[ks][1] = h2scaleq(q1[ks * 8 + tig]);
            qf[ks][2] = h2scaleq(q0[ks * 8 + tig + 4]);
            qf[ks][3] = h2scaleq(q1[ks * 8 + tig + 4]);
        }
    }

    // neighbor pair list (uniform per CTA)
    int pn0[5], pn1[5];
    int pcnt = 0;
    {
        unsigned mask = 0;
        #pragma unroll
        for (int nb = 0; nb < 9; nb++) {
            int ny = cy + nb / 3 - 1, nx = cx + nb % 3 - 1;
            if ((unsigned)ny < 8u && (unsigned)nx < 8u) mask |= 1u << nb;
        }
        while (mask) {
            int a = __ffs(mask) - 1; mask &= mask - 1;
            int c = -1;
            if (mask) { c = __ffs(mask) - 1; mask &= mask - 1; }
            pn0[pcnt] = a; pn1[pcnt] = c; pcnt++;
        }
    }

    float oacc[8][4] = {};
    float li0 = 0.f, li1 = 0.f;

    // prologue: issue pair 0 into buffer 0
    issue_pair(smem_s, pn0[0], pn1[0], cy, cx, bh, vb, t);

    #pragma unroll 1
    for (int ip = 0; ip < pcnt; ip++) {
        const bool two = pn1[ip] >= 0;
        const uint32_t bofs = smem_s + (ip & 1) * 35840;

        asm volatile("cp.async.wait_group 0;" ::: "memory");
        __syncthreads();   // pair ip's data visible; all warps past iter ip-1

        // issue next pair into the other buffer (overlaps with compute below)
        if (ip + 1 < pcnt)
            issue_pair(smem_s + ((ip + 1) & 1) * 35840,
                       pn0[ip + 1], pn1[ip + 1], cy, cx, bh, vb, t);

        // --- S = Q K^T via ldmatrix B-frags: 4 k16-steps x 8 nt-pairs
        float sacc[16][4] = {};
        #pragma unroll
        for (int ks = 0; ks < 4; ks++) {
            #pragma unroll
            for (int ntp = 0; ntp < 8; ntp++) {
                uint32_t f0, f1, f2, f3;
                ldm4(f0, f1, f2, f3, bofs + kaddr_l + ntp * 2304 + ks * 32);
                mma_f16(sacc[2 * ntp],     qf[ks], f0, f1);
                mma_f16(sacc[2 * ntp + 1], qf[ks], f2, f3);
            }
        }
        if (!two) {
            #pragma unroll
            for (int nt = 8; nt < 16; nt++) {
                sacc[nt][0] = -1e30f; sacc[nt][1] = -1e30f;
                sacc[nt][2] = -1e30f; sacc[nt][3] = -1e30f;
            }
        }

        // --- unnormalized exp2 (scores bounded), P stays in registers
        #pragma unroll
        for (int nt = 0; nt < 16; nt++) {
            sacc[nt][0] = ex2(sacc[nt][0]);
            sacc[nt][1] = ex2(sacc[nt][1]);
            sacc[nt][2] = ex2(sacc[nt][2]);
            sacc[nt][3] = ex2(sacc[nt][3]);
            li0 += sacc[nt][0] + sacc[nt][1];
            li1 += sacc[nt][2] + sacc[nt][3];
        }

        // --- O += P V : pa from registers, B-frags via ldmatrix
        #pragma unroll
        for (int ks = 0; ks < 8; ks++) {
            uint32_t pa[4];
            pa[0] = pack2(sacc[2 * ks][0],     sacc[2 * ks][1]);
            pa[1] = pack2(sacc[2 * ks][2],     sacc[2 * ks][3]);
            pa[2] = pack2(sacc[2 * ks + 1][0], sacc[2 * ks + 1][1]);
            pa[3] = pack2(sacc[2 * ks + 1][2], sacc[2 * ks + 1][3]);
            #pragma unroll
            for (int ntp = 0; ntp < 4; ntp++) {
                uint32_t f0, f1, f2, f3;
                ldm4(f0, f1, f2, f3, bofs + vaddr_l + ntp * 4352 + ks * 32);
                mma_f16(oacc[2 * ntp],     pa, f0, f1);
                mma_f16(oacc[2 * ntp + 1], pa, f2, f3);
            }
        }
    }

    li0 += __shfl_xor_sync(0xffffffffu, li0, 1);
    li0 += __shfl_xor_sync(0xffffffffu, li0, 2);
    li1 += __shfl_xor_sync(0xffffffffu, li1, 1);
    li1 += __shfl_xor_sync(0xffffffffu, li1, 2);
    float inv0 = 1.0f / li0, inv1 = 1.0f / li1;

    int y0 = cy * 8 + (row0 >> 3), x0 = cx * 8 + (row0 & 7);
    int y1 = cy * 8 + (row1 >> 3), x1 = cx * 8 + (row1 & 7);
    int m0 = b * 4096 + y0 * 64 + x0;
    int m1 = b * 4096 + y1 * 64 + x1;
    #pragma unroll
    for (int nt = 0; nt < 8; nt++) {
        int k2g = h * 32 + nt * 4 + tig;
        int kc  = k2g >> 4, k2 = k2g & 15;
        g_ob[(((m0 >> 7) * 16 + kc) * 16 + k2) * 128 + (m0 & 127)] =
            __floats2half2_rn(oacc[nt][0] * inv0, oacc[nt][1] * inv0);
        g_ob[(((m1 >> 7) * 16 + kc) * 16 + k2) * 128 + (m1 & 127)] =
            __floats2half2_rn(oacc[nt][2] * inv1, oacc[nt][3] * inv1);
    }
}

// ---------------------------------------------------------------------------
extern "C" void kernel_launch(void* const* d_in, const int* in_sizes, int n_in,
                              void* d_out, int out_size)
{
    const float* x      = (const float*)d_in[0];
    const float* w_qkv  = (const float*)d_in[1];
    const float* b_qkv  = (const float*)d_in[2];
    const float* w_proj = (const float*)d_in[3];
    const float* b_proj = (const float*)d_in[4];
    float* out = (float*)d_out;

    cudaFuncSetAttribute(attn_f16, cudaFuncAttributeMaxDynamicSharedMemorySize, 71680);

    prep_wq<<<dim3(48, 16), 256>>>(w_qkv);
    prep_wp<<<dim3(16, 16), 256>>>(w_proj);

    qkv_f16<<<dim3(12, 128), 128>>>(x, b_qkv);
    attn_f16<<<2048, 128, 71680>>>();
    proj_f16<<<dim3(4, 128), 128>>>(b_proj, out);
}